// round 2
// baseline (speedup 1.0000x reference)
#include <cuda_runtime.h>
#include <cstdint>

// ---------------- problem constants ----------------
#define NN    1024
#define DD    384
#define KK    64
#define POSW  15          // A*3
#define NBINS 64
#define NDEPTH 4
#define BSZ   256         // batch block size

// ---------------- persistent device scratch ----------------
__device__ float g_based[NN * BSZ];          // 1 MB  base distance (compact, in-batch)
__device__ int   g_idx[NN * KK];             // neighbour indices
__device__ float g_local[NN * DD];           // evolving local features
__device__ float g_msg[NN * DD];             // neighbour mean message
__device__ float g_pos[NN * POSW];           // evolving positions

// ---------------- threefry2x32 (bit-exact JAX) ----------------
__host__ __device__ __forceinline__ uint32_t rotl32(uint32_t x, int r) {
    return (x << r) | (x >> (32 - r));
}

__host__ __device__ __forceinline__ void tf2x32(uint32_t k0, uint32_t k1,
                                                uint32_t x0, uint32_t x1,
                                                uint32_t& o0, uint32_t& o1) {
    uint32_t ks2 = k0 ^ k1 ^ 0x1BD11BDAu;
#define TFR(r) { x0 += x1; x1 = rotl32(x1, r); x1 ^= x0; }
    x0 += k0;  x1 += k1;
    TFR(13) TFR(15) TFR(26) TFR(6)
    x0 += k1;  x1 += ks2 + 1u;
    TFR(17) TFR(29) TFR(16) TFR(24)
    x0 += ks2; x1 += k0 + 2u;
    TFR(13) TFR(15) TFR(26) TFR(6)
    x0 += k0;  x1 += k1 + 3u;
    TFR(17) TFR(29) TFR(16) TFR(24)
    x0 += k1;  x1 += ks2 + 4u;
    TFR(13) TFR(15) TFR(26) TFR(6)
    x0 += ks2; x1 += k0 + 5u;
#undef TFR
    o0 = x0; o1 = x1;
}

__device__ __forceinline__ float gumbel_from_bits(uint32_t b) {
    // jax uniform: bitcast((bits>>9)|0x3F800000) - 1.0  in [0,1)
    float u = __uint_as_float(0x3F800000u | (b >> 9)) - 1.0f;
    return -logf(-logf(u + 1e-6f) + 1e-6f);
}

// ---------------- kernel: step-invariant base distance ----------------
__global__ void based_kernel(const float* __restrict__ prev_pos,
                             const float* __restrict__ disto,
                             const int* __restrict__ resi,
                             const int* __restrict__ chain,
                             const int* __restrict__ batch) {
    int gid = blockIdx.x * blockDim.x + threadIdx.x;
    if (gid >= NN * BSZ) return;
    int i  = gid >> 8;
    int jj = gid & 255;
    int b  = batch[i];
    int j  = b * BSZ + jj;

    // expected distance from distogram row (softmax * centers)
    const float4* dp = (const float4*)(disto + ((size_t)i * NN + j) * NBINS);
    float4 v[16];
    float mx = -1e30f;
#pragma unroll
    for (int q = 0; q < 16; q++) {
        v[q] = dp[q];
        mx = fmaxf(mx, fmaxf(fmaxf(v[q].x, v[q].y), fmaxf(v[q].z, v[q].w)));
    }
    const float step = 22.0f / 64.0f;
    float se = 0.0f, swc = 0.0f;
#pragma unroll
    for (int q = 0; q < 16; q++) {
        float e0 = expf(v[q].x - mx), e1 = expf(v[q].y - mx);
        float e2 = expf(v[q].z - mx), e3 = expf(v[q].w - mx);
        se  += e0 + e1 + e2 + e3;
        swc += e0 * (step * (4*q + 0) + 0.5f*step)
             + e1 * (step * (4*q + 1) + 0.5f*step)
             + e2 * (step * (4*q + 2) + 0.5f*step)
             + e3 * (step * (4*q + 3) + 0.5f*step);
    }
    float md = swc / se;

    float d = __int_as_float(0x7f800000);                 // +inf
    if (chain[i] == chain[j]) {
        d = fabsf((float)(resi[i] - resi[j])) * 3.81f;
    }
    if (md < 8.0f) d = fminf(d, md);

    float dx = prev_pos[i * POSW + 3] - prev_pos[j * POSW + 3];
    float dy = prev_pos[i * POSW + 4] - prev_pos[j * POSW + 4];
    float dz = prev_pos[i * POSW + 5] - prev_pos[j * POSW + 5];
    d = fminf(d, sqrtf(dx * dx + dy * dy + dz * dz));

    g_based[gid] = d;
}

// ---------------- kernel: per-step top-K selection (gumbel fused) -----
// Partitionable-threefry gumbel: element (i,j) uses counter = i*N + j (flat
// uint64 index; hi word = 0 here), bits = o0 ^ o1.
__global__ void topk_kernel(uint32_t k0, uint32_t k1, const int* __restrict__ batch) {
    int i  = blockIdx.x;
    int jj = threadIdx.x;                                  // 256 threads
    int b  = batch[i];
    int j  = b * BSZ + jj;

    float cx = g_pos[i * POSW + 3], cy = g_pos[i * POSW + 4], cz = g_pos[i * POSW + 5];
    float dx = cx - g_pos[j * POSW + 3];
    float dy = cy - g_pos[j * POSW + 4];
    float dz = cz - g_pos[j * POSW + 5];
    float d  = fminf(g_based[i * BSZ + jj], sqrtf(dx * dx + dy * dy + dz * dz));

    uint32_t o0, o1;
    tf2x32(k0, k1, 0u, (uint32_t)(i * NN + j), o0, o1);
    float g = gumbel_from_bits(o0 ^ o1);
    float rd = 3.0f * d - g;

    // order-preserving float -> uint map, pack (value, idx): ascending sort,
    // ties resolved to lower index (matches lax.top_k)
    uint32_t ub = __float_as_uint(rd);
    ub = (ub & 0x80000000u) ? ~ub : (ub | 0x80000000u);
    unsigned long long key = ((unsigned long long)ub << 32) | (unsigned)jj;

    __shared__ unsigned long long s[BSZ];
    s[jj] = key;
    __syncthreads();

    for (unsigned k = 2; k <= BSZ; k <<= 1) {
        for (unsigned st = k >> 1; st > 0; st >>= 1) {
            unsigned ixj = jj ^ st;
            if (ixj > (unsigned)jj) {
                unsigned long long a = s[jj], c = s[ixj];
                bool up = ((jj & k) == 0);
                if ((a > c) == up) { s[jj] = c; s[ixj] = a; }
            }
            __syncthreads();
        }
    }

    if (jj < KK) {
        unsigned long long kk = s[jj];
        uint32_t mb = (uint32_t)(kk >> 32);
        int lidx = (int)(kk & 0xffffffffu);
        bool fin = mb < 0xFF800000u;                       // mapped(+inf)
        g_idx[i * KK + jj] = fin ? (b * BSZ + lidx) : -1;
    }
}

// ---------------- kernel: neighbour mean gather ----------------
__global__ void msg_kernel() {
    int i = blockIdx.x;
    int d = threadIdx.x;                                   // 384 threads
    __shared__ int sidx[KK];
    if (d < KK) sidx[d] = g_idx[i * KK + d];
    __syncthreads();
    float acc = 0.0f;
    int cnt = 0;
#pragma unroll 8
    for (int k = 0; k < KK; k++) {
        int id = sidx[k];
        if (id >= 0) { acc += g_local[id * DD + d]; cnt++; }
    }
    g_msg[i * DD + d] = acc / fmaxf((float)cnt, 1.0f);
}

// ---------------- kernel: local += gelu(msg @ Wn), 64x64x16 tiled ----------------
__device__ __forceinline__ float gelu_tanh(float x) {
    float x3 = x * x * x;
    float t = tanhf(0.7978845608028654f * (x + 0.044715f * x3));
    return 0.5f * x * (1.0f + t);
}

__global__ void gemm_gelu_kernel(const float* __restrict__ Wn) {
    const int BM = 64, BN = 64, BK = 16;
    __shared__ float As[BK][BM];
    __shared__ float Bs[BK][BN];
    int tx = threadIdx.x & 15;
    int ty = threadIdx.x >> 4;
    int row0 = blockIdx.y * BM;
    int col0 = blockIdx.x * BN;
    float acc[4][4] = {};

    for (int k0 = 0; k0 < DD; k0 += BK) {
#pragma unroll
        for (int i = 0; i < 4; i++) {
            int lin = threadIdx.x + i * 256;
            int m = lin >> 4, k = lin & 15;
            As[k][m] = g_msg[(row0 + m) * DD + k0 + k];
        }
#pragma unroll
        for (int i = 0; i < 4; i++) {
            int lin = threadIdx.x + i * 256;
            int k = lin >> 6, n = lin & 63;
            Bs[k][n] = Wn[(k0 + k) * DD + col0 + n];
        }
        __syncthreads();
#pragma unroll
        for (int k = 0; k < BK; k++) {
            float4 a = *(const float4*)&As[k][ty * 4];
            float4 bvec = *(const float4*)&Bs[k][tx * 4];
            float av[4] = {a.x, a.y, a.z, a.w};
            float bv[4] = {bvec.x, bvec.y, bvec.z, bvec.w};
#pragma unroll
            for (int ii = 0; ii < 4; ii++)
#pragma unroll
                for (int jjj = 0; jjj < 4; jjj++)
                    acc[ii][jjj] += av[ii] * bv[jjj];
        }
        __syncthreads();
    }
#pragma unroll
    for (int ii = 0; ii < 4; ii++)
#pragma unroll
        for (int jjj = 0; jjj < 4; jjj++) {
            int m = row0 + ty * 4 + ii;
            int n = col0 + tx * 4 + jjj;
            g_local[m * DD + n] += gelu_tanh(acc[ii][jjj]);
        }
}

// ---------------- kernel: pos update + trajectory write ----------------
__global__ void pos_kernel(const float* __restrict__ Wp, float* __restrict__ traj_out) {
    int i = blockIdx.x;
    __shared__ float sl[DD];
    sl[threadIdx.x] = g_local[i * DD + threadIdx.x];       // 384 threads
    __syncthreads();
    if (threadIdx.x < POSW) {
        int o = threadIdx.x;
        float acc = 0.0f;
        for (int k = 0; k < DD; k++) acc += sl[k] * Wp[k * POSW + o];
        float p = g_pos[i * POSW + o] + 0.1f * acc;
        g_pos[i * POSW + o] = p;
        traj_out[i * POSW + o] = p;
    }
}

// ---------------- launch ----------------
extern "C" void kernel_launch(void* const* d_in, const int* in_sizes, int n_in,
                              void* d_out, int out_size) {
    const float* local    = (const float*)d_in[0];
    const float* pos      = (const float*)d_in[1];
    const float* prev_pos = (const float*)d_in[2];
    const float* disto    = (const float*)d_in[3];
    const float* Wn       = (const float*)d_in[4];
    const float* Wp       = (const float*)d_in[5];
    const int*   resi     = (const int*)d_in[6];
    const int*   chain    = (const int*)d_in[7];
    const int*   batch    = (const int*)d_in[8];
    float* out = (float*)d_out;

    // init evolving state
    cudaMemcpyToSymbolAsync(g_local, local, (size_t)NN * DD * sizeof(float), 0,
                            cudaMemcpyDeviceToDevice, 0);
    cudaMemcpyToSymbolAsync(g_pos, pos, (size_t)NN * POSW * sizeof(float), 0,
                            cudaMemcpyDeviceToDevice, 0);

    based_kernel<<<NN * BSZ / 256, 256>>>(prev_pos, disto, resi, chain, batch);

    // host-side fold_in: key(42) = (0,42); folded_t = threefry2x32((0,42),(0,t))
    uint32_t fk0[NDEPTH], fk1[NDEPTH];
    for (int t = 0; t < NDEPTH; t++)
        tf2x32(0u, 42u, 0u, (uint32_t)t, fk0[t], fk1[t]);

    float* traj_base = out + (size_t)NN * DD + (size_t)NN * POSW;
    dim3 ggrid(DD / 64, NN / 64);

    for (int t = 0; t < NDEPTH; t++) {
        topk_kernel<<<NN, BSZ>>>(fk0[t], fk1[t], batch);
        msg_kernel<<<NN, DD>>>();
        gemm_gelu_kernel<<<ggrid, 256>>>(Wn);
        pos_kernel<<<NN, DD>>>(Wp, traj_base + (size_t)t * NN * POSW);
    }

    cudaMemcpyFromSymbolAsync(out, g_local, (size_t)NN * DD * sizeof(float), 0,
                              cudaMemcpyDeviceToDevice, 0);
    cudaMemcpyFromSymbolAsync(out + (size_t)NN * DD, g_pos,
                              (size_t)NN * POSW * sizeof(float), 0,
                              cudaMemcpyDeviceToDevice, 0);
}

// round 3
// speedup vs baseline: 1.1052x; 1.1052x over previous
#include <cuda_runtime.h>
#include <cstdint>

// ---------------- problem constants ----------------
#define NN    1024
#define DD    384
#define KK    64
#define POSW  15          // A*3
#define NBINS 64
#define NDEPTH 4
#define BSZ   256         // batch block size

// ---------------- persistent device scratch ----------------
__device__ float g_based[NN * BSZ];          // 1 MB  base distance (compact, in-batch)
__device__ int   g_idx[NN * KK];             // neighbour indices
__device__ float g_local[NN * DD];           // evolving local features
__device__ float g_msg[NN * DD];             // neighbour mean message
__device__ float g_pos[NN * POSW];           // evolving positions

// ---------------- threefry2x32 (bit-exact JAX) ----------------
__host__ __device__ __forceinline__ uint32_t rotl32(uint32_t x, int r) {
    return (x << r) | (x >> (32 - r));
}

__host__ __device__ __forceinline__ void tf2x32(uint32_t k0, uint32_t k1,
                                                uint32_t x0, uint32_t x1,
                                                uint32_t& o0, uint32_t& o1) {
    uint32_t ks2 = k0 ^ k1 ^ 0x1BD11BDAu;
#define TFR(r) { x0 += x1; x1 = rotl32(x1, r); x1 ^= x0; }
    x0 += k0;  x1 += k1;
    TFR(13) TFR(15) TFR(26) TFR(6)
    x0 += k1;  x1 += ks2 + 1u;
    TFR(17) TFR(29) TFR(16) TFR(24)
    x0 += ks2; x1 += k0 + 2u;
    TFR(13) TFR(15) TFR(26) TFR(6)
    x0 += k0;  x1 += k1 + 3u;
    TFR(17) TFR(29) TFR(16) TFR(24)
    x0 += k1;  x1 += ks2 + 4u;
    TFR(13) TFR(15) TFR(26) TFR(6)
    x0 += ks2; x1 += k0 + 5u;
#undef TFR
    o0 = x0; o1 = x1;
}

__device__ __forceinline__ float gumbel_from_bits(uint32_t b) {
    // jax uniform: bitcast((bits>>9)|0x3F800000) - 1.0  in [0,1)
    float u = __uint_as_float(0x3F800000u | (b >> 9)) - 1.0f;
    return -logf(-logf(u + 1e-6f) + 1e-6f);
}

// ---------------- kernel: step-invariant base distance ----------------
__global__ void based_kernel(const float* __restrict__ prev_pos,
                             const float* __restrict__ disto,
                             const int* __restrict__ resi,
                             const int* __restrict__ chain,
                             const int* __restrict__ batch) {
    int gid = blockIdx.x * blockDim.x + threadIdx.x;
    if (gid >= NN * BSZ) return;
    int i  = gid >> 8;
    int jj = gid & 255;
    int b  = batch[i];
    int j  = b * BSZ + jj;

    // expected distance from distogram row (softmax * centers)
    const float4* dp = (const float4*)(disto + ((size_t)i * NN + j) * NBINS);
    float4 v[16];
    float mx = -1e30f;
#pragma unroll
    for (int q = 0; q < 16; q++) {
        v[q] = dp[q];
        mx = fmaxf(mx, fmaxf(fmaxf(v[q].x, v[q].y), fmaxf(v[q].z, v[q].w)));
    }
    const float step = 22.0f / 64.0f;
    float se = 0.0f, swc = 0.0f;
#pragma unroll
    for (int q = 0; q < 16; q++) {
        float e0 = expf(v[q].x - mx), e1 = expf(v[q].y - mx);
        float e2 = expf(v[q].z - mx), e3 = expf(v[q].w - mx);
        se  += e0 + e1 + e2 + e3;
        swc += e0 * (step * (4*q + 0) + 0.5f*step)
             + e1 * (step * (4*q + 1) + 0.5f*step)
             + e2 * (step * (4*q + 2) + 0.5f*step)
             + e3 * (step * (4*q + 3) + 0.5f*step);
    }
    float md = swc / se;

    float d = __int_as_float(0x7f800000);                 // +inf
    if (chain[i] == chain[j]) {
        d = fabsf((float)(resi[i] - resi[j])) * 3.81f;
    }
    if (md < 8.0f) d = fminf(d, md);

    float dx = prev_pos[i * POSW + 3] - prev_pos[j * POSW + 3];
    float dy = prev_pos[i * POSW + 4] - prev_pos[j * POSW + 4];
    float dz = prev_pos[i * POSW + 5] - prev_pos[j * POSW + 5];
    d = fminf(d, sqrtf(dx * dx + dy * dy + dz * dz));

    g_based[gid] = d;
}

// ---------------- kernel: per-step top-K selection (gumbel fused) -----
__global__ void topk_kernel(uint32_t k0, uint32_t k1, const int* __restrict__ batch) {
    int i  = blockIdx.x;
    int jj = threadIdx.x;                                  // 256 threads
    int b  = batch[i];
    int j  = b * BSZ + jj;

    float cx = g_pos[i * POSW + 3], cy = g_pos[i * POSW + 4], cz = g_pos[i * POSW + 5];
    float dx = cx - g_pos[j * POSW + 3];
    float dy = cy - g_pos[j * POSW + 4];
    float dz = cz - g_pos[j * POSW + 5];
    float d  = fminf(g_based[i * BSZ + jj], sqrtf(dx * dx + dy * dy + dz * dz));

    uint32_t o0, o1;
    tf2x32(k0, k1, 0u, (uint32_t)(i * NN + j), o0, o1);
    float g = gumbel_from_bits(o0 ^ o1);
    float rd = 3.0f * d - g;

    uint32_t ub = __float_as_uint(rd);
    ub = (ub & 0x80000000u) ? ~ub : (ub | 0x80000000u);
    unsigned long long key = ((unsigned long long)ub << 32) | (unsigned)jj;

    __shared__ unsigned long long s[BSZ];
    s[jj] = key;
    __syncthreads();

    for (unsigned k = 2; k <= BSZ; k <<= 1) {
        for (unsigned st = k >> 1; st > 0; st >>= 1) {
            unsigned ixj = jj ^ st;
            if (ixj > (unsigned)jj) {
                unsigned long long a = s[jj], c = s[ixj];
                bool up = ((jj & k) == 0);
                if ((a > c) == up) { s[jj] = c; s[ixj] = a; }
            }
            __syncthreads();
        }
    }

    if (jj < KK) {
        unsigned long long kk = s[jj];
        uint32_t mb = (uint32_t)(kk >> 32);
        int lidx = (int)(kk & 0xffffffffu);
        bool fin = mb < 0xFF800000u;                       // mapped(+inf)
        g_idx[i * KK + jj] = fin ? (b * BSZ + lidx) : -1;
    }
}

// ---------------- kernel: neighbour mean gather ----------------
__global__ void msg_kernel() {
    int i = blockIdx.x;
    int d = threadIdx.x;                                   // 384 threads
    __shared__ int sidx[KK];
    if (d < KK) sidx[d] = g_idx[i * KK + d];
    __syncthreads();
    float acc = 0.0f;
    int cnt = 0;
#pragma unroll 8
    for (int k = 0; k < KK; k++) {
        int id = sidx[k];
        if (id >= 0) { acc += g_local[id * DD + d]; cnt++; }
    }
    g_msg[i * DD + d] = acc / fmaxf((float)cnt, 1.0f);
}

// ---------------- tf32 tensor-core GEMM: local += gelu(msg @ Wn) ------
__device__ __forceinline__ float gelu_tanh(float x) {
    float x3 = x * x * x;
    float t = tanhf(0.7978845608028654f * (x + 0.044715f * x3));
    return 0.5f * x * (1.0f + t);
}

__device__ __forceinline__ uint32_t to_tf32(float x) {
    uint32_t r;
    asm("cvt.rna.tf32.f32 %0, %1;" : "=r"(r) : "f"(x));
    return r;
}

__device__ __forceinline__ void mma_tf32(float* c, const uint32_t* a, const uint32_t* b) {
    asm volatile(
        "mma.sync.aligned.m16n8k8.row.col.f32.tf32.tf32.f32 "
        "{%0,%1,%2,%3},{%4,%5,%6,%7},{%8,%9},{%0,%1,%2,%3};"
        : "+f"(c[0]), "+f"(c[1]), "+f"(c[2]), "+f"(c[3])
        : "r"(a[0]), "r"(a[1]), "r"(a[2]), "r"(a[3]), "r"(b[0]), "r"(b[1]));
}

#define GBK 32
#define AST 36   // As[m][k] stride: (4m+k)%32 is a permutation -> conflict-free
#define BST 36   // Bs[n][k] stride

__global__ void __launch_bounds__(128) gemm_gelu_tc(const float* __restrict__ Wn) {
    __shared__ float As[64 * AST];
    __shared__ float Bs[64 * BST];
    int tid  = threadIdx.x;
    int warp = tid >> 5, lane = tid & 31;
    int wm = (warp & 1) * 32;          // warp tile origin within 64x64 block tile
    int wn = (warp >> 1) * 32;
    int row0 = blockIdx.y * 64;
    int col0 = blockIdx.x * 64;
    int g  = lane >> 2;                // groupID
    int tg = lane & 3;                 // thread-in-group

    float acc[2][4][4] = {};           // [mi][nj][reg]

    for (int k0 = 0; k0 < DD; k0 += GBK) {
        // stage A: 64x32 from g_msg (float4 rows)
        {
            int m  = tid >> 3;
            int kk = (tid & 7) * 4;
#pragma unroll
            for (int p = 0; p < 4; p++) {
                int mm = m + p * 16;
                float4 v = *(const float4*)&g_msg[(row0 + mm) * DD + k0 + kk];
                *(float4*)&As[mm * AST + kk] = v;
            }
        }
        // stage B: Bs[n][k] = Wn[(k0+k)*DD + col0+n]
        {
            int n = tid & 63;
            int k = tid >> 6;
#pragma unroll
            for (int p = 0; p < 16; p++) {
                int kk = k + p * 2;
                Bs[n * BST + kk] = Wn[(size_t)(k0 + kk) * DD + col0 + n];
            }
        }
        __syncthreads();

#pragma unroll
        for (int ks = 0; ks < GBK; ks += 8) {
            float af[2][4], bf[4][2];
#pragma unroll
            for (int mi = 0; mi < 2; mi++) {
                int mb = wm + mi * 16;
                af[mi][0] = As[(mb + g) * AST + ks + tg];
                af[mi][1] = As[(mb + g + 8) * AST + ks + tg];
                af[mi][2] = As[(mb + g) * AST + ks + tg + 4];
                af[mi][3] = As[(mb + g + 8) * AST + ks + tg + 4];
            }
#pragma unroll
            for (int nj = 0; nj < 4; nj++) {
                int nb = wn + nj * 8;
                bf[nj][0] = Bs[(nb + g) * BST + ks + tg];
                bf[nj][1] = Bs[(nb + g) * BST + ks + tg + 4];
            }
            // 3xTF32 split
            uint32_t ah[2][4], al[2][4], bh[4][2], bl[4][2];
#pragma unroll
            for (int mi = 0; mi < 2; mi++)
#pragma unroll
                for (int q = 0; q < 4; q++) {
                    uint32_t h = to_tf32(af[mi][q]);
                    ah[mi][q] = h;
                    al[mi][q] = to_tf32(af[mi][q] - __uint_as_float(h));
                }
#pragma unroll
            for (int nj = 0; nj < 4; nj++)
#pragma unroll
                for (int q = 0; q < 2; q++) {
                    uint32_t h = to_tf32(bf[nj][q]);
                    bh[nj][q] = h;
                    bl[nj][q] = to_tf32(bf[nj][q] - __uint_as_float(h));
                }
#pragma unroll
            for (int mi = 0; mi < 2; mi++)
#pragma unroll
                for (int nj = 0; nj < 4; nj++) {
                    mma_tf32(acc[mi][nj], al[mi], bh[nj]);
                    mma_tf32(acc[mi][nj], ah[mi], bl[nj]);
                    mma_tf32(acc[mi][nj], ah[mi], bh[nj]);
                }
        }
        __syncthreads();
    }

    // epilogue: local += gelu(acc)
#pragma unroll
    for (int mi = 0; mi < 2; mi++)
#pragma unroll
        for (int nj = 0; nj < 4; nj++) {
            int r = row0 + wm + mi * 16 + g;
            int c = col0 + wn + nj * 8 + 2 * tg;
            float* p0 = &g_local[r * DD + c];
            float* p1 = &g_local[(r + 8) * DD + c];
            p0[0] += gelu_tanh(acc[mi][nj][0]);
            p0[1] += gelu_tanh(acc[mi][nj][1]);
            p1[0] += gelu_tanh(acc[mi][nj][2]);
            p1[1] += gelu_tanh(acc[mi][nj][3]);
        }
}

// ---------------- kernel: pos update + trajectory write ----------------
__global__ void pos_kernel(const float* __restrict__ Wp, float* __restrict__ traj_out) {
    int i = blockIdx.x;
    __shared__ float sl[DD];
    sl[threadIdx.x] = g_local[i * DD + threadIdx.x];       // 384 threads
    __syncthreads();
    if (threadIdx.x < POSW) {
        int o = threadIdx.x;
        float acc = 0.0f;
        for (int k = 0; k < DD; k++) acc += sl[k] * Wp[k * POSW + o];
        float p = g_pos[i * POSW + o] + 0.1f * acc;
        g_pos[i * POSW + o] = p;
        traj_out[i * POSW + o] = p;
    }
}

// ---------------- launch ----------------
extern "C" void kernel_launch(void* const* d_in, const int* in_sizes, int n_in,
                              void* d_out, int out_size) {
    const float* local    = (const float*)d_in[0];
    const float* pos      = (const float*)d_in[1];
    const float* prev_pos = (const float*)d_in[2];
    const float* disto    = (const float*)d_in[3];
    const float* Wn       = (const float*)d_in[4];
    const float* Wp       = (const float*)d_in[5];
    const int*   resi     = (const int*)d_in[6];
    const int*   chain    = (const int*)d_in[7];
    const int*   batch    = (const int*)d_in[8];
    float* out = (float*)d_out;

    cudaMemcpyToSymbolAsync(g_local, local, (size_t)NN * DD * sizeof(float), 0,
                            cudaMemcpyDeviceToDevice, 0);
    cudaMemcpyToSymbolAsync(g_pos, pos, (size_t)NN * POSW * sizeof(float), 0,
                            cudaMemcpyDeviceToDevice, 0);

    based_kernel<<<NN * BSZ / 256, 256>>>(prev_pos, disto, resi, chain, batch);

    uint32_t fk0[NDEPTH], fk1[NDEPTH];
    for (int t = 0; t < NDEPTH; t++)
        tf2x32(0u, 42u, 0u, (uint32_t)t, fk0[t], fk1[t]);

    float* traj_base = out + (size_t)NN * DD + (size_t)NN * POSW;
    dim3 ggrid(DD / 64, NN / 64);

    for (int t = 0; t < NDEPTH; t++) {
        topk_kernel<<<NN, BSZ>>>(fk0[t], fk1[t], batch);
        msg_kernel<<<NN, DD>>>();
        gemm_gelu_tc<<<ggrid, 128>>>(Wn);
        pos_kernel<<<NN, DD>>>(Wp, traj_base + (size_t)t * NN * POSW);
    }

    cudaMemcpyFromSymbolAsync(out, g_local, (size_t)NN * DD * sizeof(float), 0,
                              cudaMemcpyDeviceToDevice, 0);
    cudaMemcpyFromSymbolAsync(out + (size_t)NN * DD, g_pos,
                              (size_t)NN * POSW * sizeof(float), 0,
                              cudaMemcpyDeviceToDevice, 0);
}

// round 4
// speedup vs baseline: 1.2498x; 1.1308x over previous
#include <cuda_runtime.h>
#include <cstdint>

// ---------------- problem constants ----------------
#define NN    1024
#define DD    384
#define KK    64
#define POSW  15          // A*3
#define NBINS 64
#define NDEPTH 4
#define BSZ   256         // batch block size

// ---------------- persistent device scratch ----------------
__device__ float g_based[NN * BSZ];          // 1 MB  base distance (compact, in-batch)
__device__ float g_local[NN * DD];           // evolving local features
__device__ float g_msg[NN * DD];             // neighbour mean message
__device__ float g_pos[NN * POSW];           // evolving positions

// ---------------- threefry2x32 (bit-exact JAX) ----------------
__host__ __device__ __forceinline__ uint32_t rotl32(uint32_t x, int r) {
    return (x << r) | (x >> (32 - r));
}

__host__ __device__ __forceinline__ void tf2x32(uint32_t k0, uint32_t k1,
                                                uint32_t x0, uint32_t x1,
                                                uint32_t& o0, uint32_t& o1) {
    uint32_t ks2 = k0 ^ k1 ^ 0x1BD11BDAu;
#define TFR(r) { x0 += x1; x1 = rotl32(x1, r); x1 ^= x0; }
    x0 += k0;  x1 += k1;
    TFR(13) TFR(15) TFR(26) TFR(6)
    x0 += k1;  x1 += ks2 + 1u;
    TFR(17) TFR(29) TFR(16) TFR(24)
    x0 += ks2; x1 += k0 + 2u;
    TFR(13) TFR(15) TFR(26) TFR(6)
    x0 += k0;  x1 += k1 + 3u;
    TFR(17) TFR(29) TFR(16) TFR(24)
    x0 += k1;  x1 += ks2 + 4u;
    TFR(13) TFR(15) TFR(26) TFR(6)
    x0 += ks2; x1 += k0 + 5u;
#undef TFR
    o0 = x0; o1 = x1;
}

__device__ __forceinline__ float gumbel_from_bits(uint32_t b) {
    float u = __uint_as_float(0x3F800000u | (b >> 9)) - 1.0f;
    return -logf(-logf(u + 1e-6f) + 1e-6f);
}

// ---------------- kernel: step-invariant base distance ----------------
__global__ void based_kernel(const float* __restrict__ prev_pos,
                             const float* __restrict__ disto,
                             const int* __restrict__ resi,
                             const int* __restrict__ chain,
                             const int* __restrict__ batch) {
    int gid = blockIdx.x * blockDim.x + threadIdx.x;
    if (gid >= NN * BSZ) return;
    int i  = gid >> 8;
    int jj = gid & 255;
    int b  = batch[i];
    int j  = b * BSZ + jj;

    const float4* dp = (const float4*)(disto + ((size_t)i * NN + j) * NBINS);
    float4 v[16];
    float mx = -1e30f;
#pragma unroll
    for (int q = 0; q < 16; q++) {
        v[q] = dp[q];
        mx = fmaxf(mx, fmaxf(fmaxf(v[q].x, v[q].y), fmaxf(v[q].z, v[q].w)));
    }
    const float step = 22.0f / 64.0f;
    float se = 0.0f, swc = 0.0f;
#pragma unroll
    for (int q = 0; q < 16; q++) {
        float e0 = expf(v[q].x - mx), e1 = expf(v[q].y - mx);
        float e2 = expf(v[q].z - mx), e3 = expf(v[q].w - mx);
        se  += e0 + e1 + e2 + e3;
        swc += e0 * (step * (4*q + 0) + 0.5f*step)
             + e1 * (step * (4*q + 1) + 0.5f*step)
             + e2 * (step * (4*q + 2) + 0.5f*step)
             + e3 * (step * (4*q + 3) + 0.5f*step);
    }
    float md = swc / se;

    float d = __int_as_float(0x7f800000);
    if (chain[i] == chain[j]) {
        d = fabsf((float)(resi[i] - resi[j])) * 3.81f;
    }
    if (md < 8.0f) d = fminf(d, md);

    float dx = prev_pos[i * POSW + 3] - prev_pos[j * POSW + 3];
    float dy = prev_pos[i * POSW + 4] - prev_pos[j * POSW + 4];
    float dz = prev_pos[i * POSW + 5] - prev_pos[j * POSW + 5];
    d = fminf(d, sqrtf(dx * dx + dy * dy + dz * dz));

    g_based[gid] = d;
}

// -------- fused top-K selection + neighbour-mean gather (384 thr) ------
__global__ void __launch_bounds__(384) topk_msg_kernel(uint32_t k0, uint32_t k1,
                                                       const int* __restrict__ batch) {
    int i   = blockIdx.x;
    int tid = threadIdx.x;
    int b   = batch[i];

    __shared__ unsigned long long s[BSZ];
    __shared__ int sidx[KK];

    if (tid < BSZ) {
        int jj = tid;
        int j  = b * BSZ + jj;
        float cx = g_pos[i * POSW + 3], cy = g_pos[i * POSW + 4], cz = g_pos[i * POSW + 5];
        float dx = cx - g_pos[j * POSW + 3];
        float dy = cy - g_pos[j * POSW + 4];
        float dz = cz - g_pos[j * POSW + 5];
        float d  = fminf(g_based[i * BSZ + jj], sqrtf(dx * dx + dy * dy + dz * dz));

        uint32_t o0, o1;
        tf2x32(k0, k1, 0u, (uint32_t)(i * NN + j), o0, o1);
        float g = gumbel_from_bits(o0 ^ o1);
        float rd = 3.0f * d - g;

        uint32_t ub = __float_as_uint(rd);
        ub = (ub & 0x80000000u) ? ~ub : (ub | 0x80000000u);
        s[jj] = ((unsigned long long)ub << 32) | (unsigned)jj;
    }
    __syncthreads();

    for (unsigned k = 2; k <= BSZ; k <<= 1) {
        for (unsigned st = k >> 1; st > 0; st >>= 1) {
            if (tid < BSZ) {
                unsigned ixj = tid ^ st;
                if (ixj > (unsigned)tid) {
                    unsigned long long a = s[tid], c = s[ixj];
                    bool up = ((tid & k) == 0);
                    if ((a > c) == up) { s[tid] = c; s[ixj] = a; }
                }
            }
            __syncthreads();
        }
    }

    if (tid < KK) {
        unsigned long long kk = s[tid];
        uint32_t mb = (uint32_t)(kk >> 32);
        int lidx = (int)(kk & 0xffffffffu);
        sidx[tid] = (mb < 0xFF800000u) ? (b * BSZ + lidx) : -1;
    }
    __syncthreads();

    // neighbour mean: thread d handles feature column d
    float acc = 0.0f;
    int cnt = 0;
#pragma unroll 8
    for (int k = 0; k < KK; k++) {
        int id = sidx[k];
        if (id >= 0) { acc += g_local[id * DD + tid]; cnt++; }
    }
    g_msg[i * DD + tid] = acc / fmaxf((float)cnt, 1.0f);
}

// ---------------- tf32 tensor-core GEMM: local += gelu(msg @ Wn) ------
__device__ __forceinline__ float gelu_tanh(float x) {
    float x3 = x * x * x;
    float t = tanhf(0.7978845608028654f * (x + 0.044715f * x3));
    return 0.5f * x * (1.0f + t);
}

__device__ __forceinline__ uint32_t to_tf32(float x) {
    uint32_t r;
    asm("cvt.rna.tf32.f32 %0, %1;" : "=r"(r) : "f"(x));
    return r;
}

__device__ __forceinline__ void mma_tf32(float* c, const uint32_t* a, const uint32_t* b) {
    asm volatile(
        "mma.sync.aligned.m16n8k8.row.col.f32.tf32.tf32.f32 "
        "{%0,%1,%2,%3},{%4,%5,%6,%7},{%8,%9},{%0,%1,%2,%3};"
        : "+f"(c[0]), "+f"(c[1]), "+f"(c[2]), "+f"(c[3])
        : "r"(a[0]), "r"(a[1]), "r"(a[2]), "r"(a[3]), "r"(b[0]), "r"(b[1]));
}

#define GBK  32
#define AST  36   // As[m][k] pad: (4g+tg)%32 permutation -> conflict-free
#define BSTN 72   // Bs[k][n] pad: (8tg+g)%32 permutation -> conflict-free
#define NKIT (DD / GBK)   // 12

__global__ void __launch_bounds__(256) gemm_gelu_tc(const float* __restrict__ Wn) {
    __shared__ float As[2][64 * AST];
    __shared__ float Bs[2][GBK * BSTN];

    int tid  = threadIdx.x;
    int warp = tid >> 5, lane = tid & 31;
    int wm = (warp & 3) * 16;            // 8 warps: 4 along M, 2 along N
    int wn = (warp >> 2) * 32;
    int row0 = blockIdx.y * 64;
    int col0 = blockIdx.x * 64;
    int g  = lane >> 2;
    int tg = lane & 3;

    float acc[4][4] = {};                // [nj][reg], warp tile 16x32

    // staging coordinates (256 threads)
    int am = tid >> 2;                   // 0..63  (A row)
    int ak = (tid & 3) * 8;              // 0,8,16,24
    int bk = tid >> 3;                   // 0..31  (B k-row)
    int bn = (tid & 7) * 8;              // 0..56

    uint32_t sa0 = (uint32_t)__cvta_generic_to_shared(&As[0][am * AST + ak]);
    uint32_t sa1 = (uint32_t)__cvta_generic_to_shared(&As[1][am * AST + ak]);
    uint32_t sb0 = (uint32_t)__cvta_generic_to_shared(&Bs[0][bk * BSTN + bn]);
    uint32_t sb1 = (uint32_t)__cvta_generic_to_shared(&Bs[1][bk * BSTN + bn]);

#define STAGE(it, SA, SB)                                                        \
    {                                                                            \
        int k0 = (it) * GBK;                                                     \
        const float* gp = &g_msg[(row0 + am) * DD + k0 + ak];                    \
        asm volatile("cp.async.cg.shared.global [%0],[%1],16;" :: "r"(SA), "l"(gp)); \
        asm volatile("cp.async.cg.shared.global [%0],[%1],16;" :: "r"(SA + 16), "l"(gp + 4)); \
        const float* gq = &Wn[(size_t)(k0 + bk) * DD + col0 + bn];               \
        asm volatile("cp.async.cg.shared.global [%0],[%1],16;" :: "r"(SB), "l"(gq)); \
        asm volatile("cp.async.cg.shared.global [%0],[%1],16;" :: "r"(SB + 16), "l"(gq + 4)); \
        asm volatile("cp.async.commit_group;");                                  \
    }

    STAGE(0, sa0, sb0)

    for (int it = 0; it < NKIT; ++it) {
        int cur = it & 1;
        if (it + 1 < NKIT) {
            if (cur) STAGE(it + 1, sa0, sb0)
            else     STAGE(it + 1, sa1, sb1)
            asm volatile("cp.async.wait_group 1;");
        } else {
            asm volatile("cp.async.wait_group 0;");
        }
        __syncthreads();

        const float* A = As[cur];
        const float* B = Bs[cur];
#pragma unroll
        for (int ks = 0; ks < GBK; ks += 8) {
            float a0 = A[(wm + g) * AST + ks + tg];
            float a1 = A[(wm + g + 8) * AST + ks + tg];
            float a2 = A[(wm + g) * AST + ks + tg + 4];
            float a3 = A[(wm + g + 8) * AST + ks + tg + 4];
            uint32_t ah[4] = { to_tf32(a0), to_tf32(a1), to_tf32(a2), to_tf32(a3) };
            uint32_t al[4] = { to_tf32(a0 - __uint_as_float(ah[0])),
                               to_tf32(a1 - __uint_as_float(ah[1])),
                               to_tf32(a2 - __uint_as_float(ah[2])),
                               to_tf32(a3 - __uint_as_float(ah[3])) };
#pragma unroll
            for (int nj = 0; nj < 4; nj++) {
                float b0 = B[(ks + tg) * BSTN + wn + nj * 8 + g];
                float b1 = B[(ks + tg + 4) * BSTN + wn + nj * 8 + g];
                uint32_t bh[2] = { to_tf32(b0), to_tf32(b1) };
                uint32_t bl[2] = { to_tf32(b0 - __uint_as_float(bh[0])),
                                   to_tf32(b1 - __uint_as_float(bh[1])) };
                mma_tf32(acc[nj], al, bh);
                mma_tf32(acc[nj], ah, bl);
                mma_tf32(acc[nj], ah, bh);
            }
        }
        __syncthreads();
    }

    // epilogue: local += gelu(acc)
#pragma unroll
    for (int nj = 0; nj < 4; nj++) {
        int r = row0 + wm + g;
        int c = col0 + wn + nj * 8 + 2 * tg;
        g_local[r * DD + c]           += gelu_tanh(acc[nj][0]);
        g_local[r * DD + c + 1]       += gelu_tanh(acc[nj][1]);
        g_local[(r + 8) * DD + c]     += gelu_tanh(acc[nj][2]);
        g_local[(r + 8) * DD + c + 1] += gelu_tanh(acc[nj][3]);
    }
}

// ---------------- kernel: pos update + trajectory write ----------------
__global__ void __launch_bounds__(384) pos_kernel(const float* __restrict__ Wp,
                                                  float* __restrict__ traj_out) {
    int i = blockIdx.x;
    int t = threadIdx.x;                 // 384 threads, one per feature
    int warp = t >> 5, lane = t & 31;

    float v = g_local[i * DD + t];
    float p[POSW];
#pragma unroll
    for (int o = 0; o < POSW; o++) p[o] = v * Wp[t * POSW + o];

#pragma unroll
    for (int s = 16; s > 0; s >>= 1)
#pragma unroll
        for (int o = 0; o < POSW; o++)
            p[o] += __shfl_down_sync(0xFFFFFFFFu, p[o], s);

    __shared__ float ws[12][POSW];
    if (lane == 0)
#pragma unroll
        for (int o = 0; o < POSW; o++) ws[warp][o] = p[o];
    __syncthreads();

    if (t < POSW) {
        float acc = 0.0f;
#pragma unroll
        for (int w = 0; w < 12; w++) acc += ws[w][t];
        float np = g_pos[i * POSW + t] + 0.1f * acc;
        g_pos[i * POSW + t] = np;
        traj_out[i * POSW + t] = np;
    }
}

// ---------------- launch ----------------
extern "C" void kernel_launch(void* const* d_in, const int* in_sizes, int n_in,
                              void* d_out, int out_size) {
    const float* local    = (const float*)d_in[0];
    const float* pos      = (const float*)d_in[1];
    const float* prev_pos = (const float*)d_in[2];
    const float* disto    = (const float*)d_in[3];
    const float* Wn       = (const float*)d_in[4];
    const float* Wp       = (const float*)d_in[5];
    const int*   resi     = (const int*)d_in[6];
    const int*   chain    = (const int*)d_in[7];
    const int*   batch    = (const int*)d_in[8];
    float* out = (float*)d_out;

    cudaMemcpyToSymbolAsync(g_local, local, (size_t)NN * DD * sizeof(float), 0,
                            cudaMemcpyDeviceToDevice, 0);
    cudaMemcpyToSymbolAsync(g_pos, pos, (size_t)NN * POSW * sizeof(float), 0,
                            cudaMemcpyDeviceToDevice, 0);

    based_kernel<<<NN * BSZ / 256, 256>>>(prev_pos, disto, resi, chain, batch);

    uint32_t fk0[NDEPTH], fk1[NDEPTH];
    for (int t = 0; t < NDEPTH; t++)
        tf2x32(0u, 42u, 0u, (uint32_t)t, fk0[t], fk1[t]);

    float* traj_base = out + (size_t)NN * DD + (size_t)NN * POSW;
    dim3 ggrid(DD / 64, NN / 64);

    for (int t = 0; t < NDEPTH; t++) {
        topk_msg_kernel<<<NN, 384>>>(fk0[t], fk1[t], batch);
        gemm_gelu_tc<<<ggrid, 256>>>(Wn);
        pos_kernel<<<NN, 384>>>(Wp, traj_base + (size_t)t * NN * POSW);
    }

    cudaMemcpyFromSymbolAsync(out, g_local, (size_t)NN * DD * sizeof(float), 0,
                              cudaMemcpyDeviceToDevice, 0);
    cudaMemcpyFromSymbolAsync(out + (size_t)NN * DD, g_pos,
                              (size_t)NN * POSW * sizeof(float), 0,
                              cudaMemcpyDeviceToDevice, 0);
}

// round 6
// speedup vs baseline: 1.4197x; 1.1359x over previous
#include <cuda_runtime.h>
#include <cstdint>

// ---------------- problem constants ----------------
#define NN    1024
#define DD    384
#define KK    64
#define POSW  15          // A*3
#define NBINS 64
#define NDEPTH 4
#define BSZ   256         // batch block size
#define NCB   6           // column blocks in gemm (384/64)
#define NPART (NCB * 2)   // pos-partial slots: col-block x warp-half

// ---------------- persistent device scratch ----------------
__device__ float g_based[NN * BSZ];             // base distance (compact, in-batch)
__device__ float g_local[NN * DD];              // evolving local features
__device__ float g_msg[NN * DD];                // neighbour mean message
__device__ float g_pos[NN * POSW];              // evolving positions
__device__ float g_pospart[NPART * NN * POSW];  // pos partials

// ---------------- threefry2x32 (bit-exact JAX) ----------------
__host__ __device__ __forceinline__ uint32_t rotl32(uint32_t x, int r) {
    return (x << r) | (x >> (32 - r));
}

__host__ __device__ __forceinline__ void tf2x32(uint32_t k0, uint32_t k1,
                                                uint32_t x0, uint32_t x1,
                                                uint32_t& o0, uint32_t& o1) {
    uint32_t ks2 = k0 ^ k1 ^ 0x1BD11BDAu;
#define TFR(r) { x0 += x1; x1 = rotl32(x1, r); x1 ^= x0; }
    x0 += k0;  x1 += k1;
    TFR(13) TFR(15) TFR(26) TFR(6)
    x0 += k1;  x1 += ks2 + 1u;
    TFR(17) TFR(29) TFR(16) TFR(24)
    x0 += ks2; x1 += k0 + 2u;
    TFR(13) TFR(15) TFR(26) TFR(6)
    x0 += k0;  x1 += k1 + 3u;
    TFR(17) TFR(29) TFR(16) TFR(24)
    x0 += k1;  x1 += ks2 + 4u;
    TFR(13) TFR(15) TFR(26) TFR(6)
    x0 += ks2; x1 += k0 + 5u;
#undef TFR
    o0 = x0; o1 = x1;
}

__device__ __forceinline__ float gumbel_from_bits(uint32_t b) {
    float u = __uint_as_float(0x3F800000u | (b >> 9)) - 1.0f;
    return -logf(-logf(u + 1e-6f) + 1e-6f);
}

// ---------------- kernel: step-invariant base distance ----------------
__global__ void based_kernel(const float* __restrict__ prev_pos,
                             const float* __restrict__ disto,
                             const int* __restrict__ resi,
                             const int* __restrict__ chain,
                             const int* __restrict__ batch) {
    int gid = blockIdx.x * blockDim.x + threadIdx.x;
    if (gid >= NN * BSZ) return;
    int i  = gid >> 8;
    int jj = gid & 255;
    int b  = batch[i];
    int j  = b * BSZ + jj;

    const float4* dp = (const float4*)(disto + ((size_t)i * NN + j) * NBINS);
    float4 v[16];
    float mx = -1e30f;
#pragma unroll
    for (int q = 0; q < 16; q++) {
        v[q] = dp[q];
        mx = fmaxf(mx, fmaxf(fmaxf(v[q].x, v[q].y), fmaxf(v[q].z, v[q].w)));
    }
    const float step = 22.0f / 64.0f;
    float se = 0.0f, swc = 0.0f;
#pragma unroll
    for (int q = 0; q < 16; q++) {
        float e0 = expf(v[q].x - mx), e1 = expf(v[q].y - mx);
        float e2 = expf(v[q].z - mx), e3 = expf(v[q].w - mx);
        se  += e0 + e1 + e2 + e3;
        swc += e0 * (step * (4*q + 0) + 0.5f*step)
             + e1 * (step * (4*q + 1) + 0.5f*step)
             + e2 * (step * (4*q + 2) + 0.5f*step)
             + e3 * (step * (4*q + 3) + 0.5f*step);
    }
    float md = swc / se;

    float d = __int_as_float(0x7f800000);
    if (chain[i] == chain[j]) {
        d = fabsf((float)(resi[i] - resi[j])) * 3.81f;
    }
    if (md < 8.0f) d = fminf(d, md);

    float dx = prev_pos[i * POSW + 3] - prev_pos[j * POSW + 3];
    float dy = prev_pos[i * POSW + 4] - prev_pos[j * POSW + 4];
    float dz = prev_pos[i * POSW + 5] - prev_pos[j * POSW + 5];
    d = fminf(d, sqrtf(dx * dx + dy * dy + dz * dz));

    g_based[gid] = d;
}

// -------- fused top-K (hybrid shfl bitonic) + neighbour-mean gather ----
__global__ void __launch_bounds__(256) topk_msg_kernel(uint32_t k0, uint32_t k1,
                                                       const int* __restrict__ batch) {
    int i   = blockIdx.x;
    int tid = threadIdx.x;                                 // 256 threads
    int b   = batch[i];

    __shared__ unsigned long long s[BSZ];
    __shared__ int sidx[KK];

    // compute selection key
    unsigned long long K;
    {
        int jj = tid;
        int j  = b * BSZ + jj;
        float cx = g_pos[i * POSW + 3], cy = g_pos[i * POSW + 4], cz = g_pos[i * POSW + 5];
        float dx = cx - g_pos[j * POSW + 3];
        float dy = cy - g_pos[j * POSW + 4];
        float dz = cz - g_pos[j * POSW + 5];
        float d  = fminf(g_based[i * BSZ + jj], sqrtf(dx * dx + dy * dy + dz * dz));

        uint32_t o0, o1;
        tf2x32(k0, k1, 0u, (uint32_t)(i * NN + j), o0, o1);
        float g = gumbel_from_bits(o0 ^ o1);
        float rd = 3.0f * d - g;

        uint32_t ub = __float_as_uint(rd);
        ub = (ub & 0x80000000u) ? ~ub : (ub | 0x80000000u);
        K = ((unsigned long long)ub << 32) | (unsigned)jj;
    }

    // bitonic sort, 1 key/thread: stride<32 via shfl, else smem
    for (unsigned k = 2; k <= BSZ; k <<= 1) {
        bool up = ((tid & k) == 0);
        for (unsigned st = k >> 1; st > 0; st >>= 1) {
            unsigned long long other;
            if (st >= 32) {
                s[tid] = K;
                __syncthreads();
                other = s[tid ^ st];
                __syncthreads();
            } else {
                other = __shfl_xor_sync(0xFFFFFFFFu, K, st);
            }
            bool lower = ((tid & st) == 0);
            bool keepmin = (up == lower);
            K = keepmin ? (K < other ? K : other) : (K > other ? K : other);
        }
    }

    if (tid < KK)
        sidx[tid] = b * BSZ + (int)(K & 0xffffffffu);
    __syncthreads();

    // neighbour mean over 64 rows (cnt == 64 always; fp32 gumbel can't be NaN/inf)
    float acc1 = 0.0f;
    float acc2 = 0.0f;
    int c2 = 256 + (tid & 127);
    bool has2 = (tid < 128);
#pragma unroll 8
    for (int k = 0; k < KK; k++) {
        int base = sidx[k] * DD;
        acc1 += g_local[base + tid];
        if (has2) acc2 += g_local[base + c2];
    }
    g_msg[i * DD + tid] = acc1 * (1.0f / 64.0f);
    if (has2) g_msg[i * DD + c2] = acc2 * (1.0f / 64.0f);
}

// -------- tf32 GEMM: local += gelu(msg @ Wn), fused pos partials -------
__device__ __forceinline__ float gelu_tanh(float x) {
    float x3 = x * x * x;
    float t = tanhf(0.7978845608028654f * (x + 0.044715f * x3));
    return 0.5f * x * (1.0f + t);
}

__device__ __forceinline__ uint32_t to_tf32(float x) {
    uint32_t r;
    asm("cvt.rna.tf32.f32 %0, %1;" : "=r"(r) : "f"(x));
    return r;
}

__device__ __forceinline__ void mma_tf32(float* c, const uint32_t* a, const uint32_t* b) {
    asm volatile(
        "mma.sync.aligned.m16n8k8.row.col.f32.tf32.tf32.f32 "
        "{%0,%1,%2,%3},{%4,%5,%6,%7},{%8,%9},{%0,%1,%2,%3};"
        : "+f"(c[0]), "+f"(c[1]), "+f"(c[2]), "+f"(c[3])
        : "r"(a[0]), "r"(a[1]), "r"(a[2]), "r"(a[3]), "r"(b[0]), "r"(b[1]));
}

#define GBK  32
#define AST  36
#define BSTN 72
#define NKIT (DD / GBK)   // 12

__global__ void __launch_bounds__(256) gemm_gelu_tc(const float* __restrict__ Wn,
                                                    const float* __restrict__ Wp) {
    __shared__ float As[2][64 * AST];
    __shared__ float Bs[2][GBK * BSTN];
    __shared__ float WpS[64 * POSW];

    int tid  = threadIdx.x;
    int warp = tid >> 5, lane = tid & 31;
    int wm = (warp & 3) * 16;            // 8 warps: 4 along M, 2 along N
    int wn = (warp >> 2) * 32;
    int row0 = blockIdx.y * 64;
    int col0 = blockIdx.x * 64;
    int g  = lane >> 2;
    int tg = lane & 3;

    float acc[4][4] = {};

    int am = tid >> 2;
    int ak = (tid & 3) * 8;
    int bk = tid >> 3;
    int bn = (tid & 7) * 8;

    uint32_t sa0 = (uint32_t)__cvta_generic_to_shared(&As[0][am * AST + ak]);
    uint32_t sa1 = (uint32_t)__cvta_generic_to_shared(&As[1][am * AST + ak]);
    uint32_t sb0 = (uint32_t)__cvta_generic_to_shared(&Bs[0][bk * BSTN + bn]);
    uint32_t sb1 = (uint32_t)__cvta_generic_to_shared(&Bs[1][bk * BSTN + bn]);

#define STAGE(it, SA, SB)                                                        \
    {                                                                            \
        int k0 = (it) * GBK;                                                     \
        const float* gp = &g_msg[(row0 + am) * DD + k0 + ak];                    \
        asm volatile("cp.async.cg.shared.global [%0],[%1],16;" :: "r"(SA), "l"(gp)); \
        asm volatile("cp.async.cg.shared.global [%0],[%1],16;" :: "r"(SA + 16), "l"(gp + 4)); \
        const float* gq = &Wn[(size_t)(k0 + bk) * DD + col0 + bn];               \
        asm volatile("cp.async.cg.shared.global [%0],[%1],16;" :: "r"(SB), "l"(gq)); \
        asm volatile("cp.async.cg.shared.global [%0],[%1],16;" :: "r"(SB + 16), "l"(gq + 4)); \
        asm volatile("cp.async.commit_group;");                                  \
    }

    STAGE(0, sa0, sb0)

    // stage Wp tile (cols col0..col0+63, all 15 outputs) — contiguous in Wp
    for (int idx = tid; idx < 64 * POSW; idx += 256)
        WpS[idx] = Wp[col0 * POSW + idx];

    for (int it = 0; it < NKIT; ++it) {
        int cur = it & 1;
        if (it + 1 < NKIT) {
            if (cur) STAGE(it + 1, sa0, sb0)
            else     STAGE(it + 1, sa1, sb1)
            asm volatile("cp.async.wait_group 1;");
        } else {
            asm volatile("cp.async.wait_group 0;");
        }
        __syncthreads();

        const float* A = As[cur];
        const float* B = Bs[cur];
#pragma unroll
        for (int ks = 0; ks < GBK; ks += 8) {
            float a0 = A[(wm + g) * AST + ks + tg];
            float a1 = A[(wm + g + 8) * AST + ks + tg];
            float a2 = A[(wm + g) * AST + ks + tg + 4];
            float a3 = A[(wm + g + 8) * AST + ks + tg + 4];
            uint32_t ah[4] = { to_tf32(a0), to_tf32(a1), to_tf32(a2), to_tf32(a3) };
            uint32_t al[4] = { to_tf32(a0 - __uint_as_float(ah[0])),
                               to_tf32(a1 - __uint_as_float(ah[1])),
                               to_tf32(a2 - __uint_as_float(ah[2])),
                               to_tf32(a3 - __uint_as_float(ah[3])) };
#pragma unroll
            for (int nj = 0; nj < 4; nj++) {
                float b0 = B[(ks + tg) * BSTN + wn + nj * 8 + g];
                float b1 = B[(ks + tg + 4) * BSTN + wn + nj * 8 + g];
                uint32_t bh[2] = { to_tf32(b0), to_tf32(b1) };
                uint32_t bl[2] = { to_tf32(b0 - __uint_as_float(bh[0])),
                                   to_tf32(b1 - __uint_as_float(bh[1])) };
                mma_tf32(acc[nj], al, bh);
                mma_tf32(acc[nj], ah, bl);
                mma_tf32(acc[nj], ah, bh);
            }
        }
        __syncthreads();
    }

    // epilogue: local += gelu(acc); accumulate pos partials over this col block
    int r = row0 + wm + g;
    float pp0[POSW], pp1[POSW];
#pragma unroll
    for (int o = 0; o < POSW; o++) { pp0[o] = 0.0f; pp1[o] = 0.0f; }

#pragma unroll
    for (int nj = 0; nj < 4; nj++) {
        int cl = wn + nj * 8 + 2 * tg;
        int c  = col0 + cl;
        float v00 = g_local[r * DD + c]           + gelu_tanh(acc[nj][0]);
        float v01 = g_local[r * DD + c + 1]       + gelu_tanh(acc[nj][1]);
        float v10 = g_local[(r + 8) * DD + c]     + gelu_tanh(acc[nj][2]);
        float v11 = g_local[(r + 8) * DD + c + 1] + gelu_tanh(acc[nj][3]);
        g_local[r * DD + c]           = v00;
        g_local[r * DD + c + 1]       = v01;
        g_local[(r + 8) * DD + c]     = v10;
        g_local[(r + 8) * DD + c + 1] = v11;
#pragma unroll
        for (int o = 0; o < POSW; o++) {
            float w0 = WpS[cl * POSW + o];
            float w1 = WpS[(cl + 1) * POSW + o];
            pp0[o] += v00 * w0 + v01 * w1;
            pp1[o] += v10 * w0 + v11 * w1;
        }
    }

    // reduce over the 4 tg lanes (same row, different columns)
#pragma unroll
    for (int dlt = 1; dlt <= 2; dlt <<= 1)
#pragma unroll
        for (int o = 0; o < POSW; o++) {
            pp0[o] += __shfl_xor_sync(0xFFFFFFFFu, pp0[o], dlt);
            pp1[o] += __shfl_xor_sync(0xFFFFFFFFu, pp1[o], dlt);
        }

    if (tg == 0) {
        // one slot per (col-block, warp N-half): rows are shared by wn=0 and
        // wn=32 warps — separate slots prevent the overwrite race
        int slot = blockIdx.x * 2 + (wn >> 5);
        float* pb = &g_pospart[(size_t)slot * (NN * POSW)];
#pragma unroll
        for (int o = 0; o < POSW; o++) {
            pb[r * POSW + o]       = pp0[o];
            pb[(r + 8) * POSW + o] = pp1[o];
        }
    }
}

// ---------------- kernel: finalize pos + trajectory write --------------
__global__ void __launch_bounds__(384) finalize_pos(float* __restrict__ traj_out) {
    int gidx = blockIdx.x * 384 + threadIdx.x;             // 40 blocks x 384 = 15360
    float acc = 0.0f;
#pragma unroll
    for (int cb = 0; cb < NPART; cb++)
        acc += g_pospart[(size_t)cb * (NN * POSW) + gidx];
    float p = g_pos[gidx] + 0.1f * acc;
    g_pos[gidx] = p;
    traj_out[gidx] = p;
}

// ---------------- launch ----------------
extern "C" void kernel_launch(void* const* d_in, const int* in_sizes, int n_in,
                              void* d_out, int out_size) {
    const float* local    = (const float*)d_in[0];
    const float* pos      = (const float*)d_in[1];
    const float* prev_pos = (const float*)d_in[2];
    const float* disto    = (const float*)d_in[3];
    const float* Wn       = (const float*)d_in[4];
    const float* Wp       = (const float*)d_in[5];
    const int*   resi     = (const int*)d_in[6];
    const int*   chain    = (const int*)d_in[7];
    const int*   batch    = (const int*)d_in[8];
    float* out = (float*)d_out;

    cudaMemcpyToSymbolAsync(g_local, local, (size_t)NN * DD * sizeof(float), 0,
                            cudaMemcpyDeviceToDevice, 0);
    cudaMemcpyToSymbolAsync(g_pos, pos, (size_t)NN * POSW * sizeof(float), 0,
                            cudaMemcpyDeviceToDevice, 0);

    based_kernel<<<NN * BSZ / 256, 256>>>(prev_pos, disto, resi, chain, batch);

    uint32_t fk0[NDEPTH], fk1[NDEPTH];
    for (int t = 0; t < NDEPTH; t++)
        tf2x32(0u, 42u, 0u, (uint32_t)t, fk0[t], fk1[t]);

    float* traj_base = out + (size_t)NN * DD + (size_t)NN * POSW;
    dim3 ggrid(DD / 64, NN / 64);

    for (int t = 0; t < NDEPTH; t++) {
        topk_msg_kernel<<<NN, BSZ>>>(fk0[t], fk1[t], batch);
        gemm_gelu_tc<<<ggrid, 256>>>(Wn, Wp);
        finalize_pos<<<NN * POSW / 384, 384>>>(traj_base + (size_t)t * NN * POSW);
    }

    cudaMemcpyFromSymbolAsync(out, g_local, (size_t)NN * DD * sizeof(float), 0,
                              cudaMemcpyDeviceToDevice, 0);
    cudaMemcpyFromSymbolAsync(out + (size_t)NN * DD, g_pos,
                              (size_t)NN * POSW * sizeof(float), 0,
                              cudaMemcpyDeviceToDevice, 0);
}

// round 7
// speedup vs baseline: 1.4416x; 1.0154x over previous
#include <cuda_runtime.h>
#include <cstdint>

// ---------------- problem constants ----------------
#define NN    1024
#define DD    384
#define KK    64
#define POSW  15          // A*3
#define NBINS 64
#define NDEPTH 4
#define BSZ   256         // batch block size
#define NCB   6           // column blocks in gemm (384/64)
#define NPART (NCB * 2)   // pos-partial slots: col-block x warp-half

// ---------------- persistent device scratch ----------------
__device__ float g_based[NN * BSZ];             // base distance (compact, in-batch)
__device__ float g_local[NN * DD];              // evolving local features
__device__ float g_msg[NN * DD];                // neighbour mean message
__device__ float g_pos[NN * POSW];              // evolving positions
__device__ float g_pospart[NPART * NN * POSW];  // pos partials
__device__ float g_S[NN * BSZ];                 // 0/1 selection matrix (per-batch cols)

// ---------------- threefry2x32 (bit-exact JAX) ----------------
__host__ __device__ __forceinline__ uint32_t rotl32(uint32_t x, int r) {
    return (x << r) | (x >> (32 - r));
}

__host__ __device__ __forceinline__ void tf2x32(uint32_t k0, uint32_t k1,
                                                uint32_t x0, uint32_t x1,
                                                uint32_t& o0, uint32_t& o1) {
    uint32_t ks2 = k0 ^ k1 ^ 0x1BD11BDAu;
#define TFR(r) { x0 += x1; x1 = rotl32(x1, r); x1 ^= x0; }
    x0 += k0;  x1 += k1;
    TFR(13) TFR(15) TFR(26) TFR(6)
    x0 += k1;  x1 += ks2 + 1u;
    TFR(17) TFR(29) TFR(16) TFR(24)
    x0 += ks2; x1 += k0 + 2u;
    TFR(13) TFR(15) TFR(26) TFR(6)
    x0 += k0;  x1 += k1 + 3u;
    TFR(17) TFR(29) TFR(16) TFR(24)
    x0 += k1;  x1 += ks2 + 4u;
    TFR(13) TFR(15) TFR(26) TFR(6)
    x0 += ks2; x1 += k0 + 5u;
#undef TFR
    o0 = x0; o1 = x1;
}

__device__ __forceinline__ float gumbel_from_bits(uint32_t b) {
    float u = __uint_as_float(0x3F800000u | (b >> 9)) - 1.0f;
    return -logf(-logf(u + 1e-6f) + 1e-6f);
}

// ---------------- kernel: step-invariant base distance ----------------
__global__ void based_kernel(const float* __restrict__ prev_pos,
                             const float* __restrict__ disto,
                             const int* __restrict__ resi,
                             const int* __restrict__ chain,
                             const int* __restrict__ batch) {
    int gid = blockIdx.x * blockDim.x + threadIdx.x;
    if (gid >= NN * BSZ) return;
    int i  = gid >> 8;
    int jj = gid & 255;
    int b  = batch[i];
    int j  = b * BSZ + jj;

    const float4* dp = (const float4*)(disto + ((size_t)i * NN + j) * NBINS);
    float4 v[16];
    float mx = -1e30f;
#pragma unroll
    for (int q = 0; q < 16; q++) {
        v[q] = dp[q];
        mx = fmaxf(mx, fmaxf(fmaxf(v[q].x, v[q].y), fmaxf(v[q].z, v[q].w)));
    }
    const float step = 22.0f / 64.0f;
    float se = 0.0f, swc = 0.0f;
#pragma unroll
    for (int q = 0; q < 16; q++) {
        float e0 = expf(v[q].x - mx), e1 = expf(v[q].y - mx);
        float e2 = expf(v[q].z - mx), e3 = expf(v[q].w - mx);
        se  += e0 + e1 + e2 + e3;
        swc += e0 * (step * (4*q + 0) + 0.5f*step)
             + e1 * (step * (4*q + 1) + 0.5f*step)
             + e2 * (step * (4*q + 2) + 0.5f*step)
             + e3 * (step * (4*q + 3) + 0.5f*step);
    }
    float md = swc / se;

    float d = __int_as_float(0x7f800000);
    if (chain[i] == chain[j]) {
        d = fabsf((float)(resi[i] - resi[j])) * 3.81f;
    }
    if (md < 8.0f) d = fminf(d, md);

    float dx = prev_pos[i * POSW + 3] - prev_pos[j * POSW + 3];
    float dy = prev_pos[i * POSW + 4] - prev_pos[j * POSW + 4];
    float dz = prev_pos[i * POSW + 5] - prev_pos[j * POSW + 5];
    d = fminf(d, sqrtf(dx * dx + dy * dy + dz * dz));

    g_based[gid] = d;
}

// -------- top-K (hybrid shfl bitonic) -> selection matrix row ----------
__global__ void __launch_bounds__(256) topk_kernel(uint32_t k0, uint32_t k1,
                                                   const int* __restrict__ batch) {
    int i   = blockIdx.x;
    int tid = threadIdx.x;                                 // 256 threads
    int b   = batch[i];

    __shared__ unsigned long long s[BSZ];
    __shared__ float srow[BSZ];

    // compute selection key
    unsigned long long K;
    {
        int jj = tid;
        int j  = b * BSZ + jj;
        float cx = g_pos[i * POSW + 3], cy = g_pos[i * POSW + 4], cz = g_pos[i * POSW + 5];
        float dx = cx - g_pos[j * POSW + 3];
        float dy = cy - g_pos[j * POSW + 4];
        float dz = cz - g_pos[j * POSW + 5];
        float d  = fminf(g_based[i * BSZ + jj], sqrtf(dx * dx + dy * dy + dz * dz));

        uint32_t o0, o1;
        tf2x32(k0, k1, 0u, (uint32_t)(i * NN + j), o0, o1);
        float g = gumbel_from_bits(o0 ^ o1);
        float rd = 3.0f * d - g;

        uint32_t ub = __float_as_uint(rd);
        ub = (ub & 0x80000000u) ? ~ub : (ub | 0x80000000u);
        K = ((unsigned long long)ub << 32) | (unsigned)jj;
    }

    srow[tid] = 0.0f;

    // bitonic sort, 1 key/thread: stride<32 via shfl, else smem
    for (unsigned k = 2; k <= BSZ; k <<= 1) {
        bool up = ((tid & k) == 0);
        for (unsigned st = k >> 1; st > 0; st >>= 1) {
            unsigned long long other;
            if (st >= 32) {
                s[tid] = K;
                __syncthreads();
                other = s[tid ^ st];
                __syncthreads();
            } else {
                other = __shfl_xor_sync(0xFFFFFFFFu, K, st);
            }
            bool lower = ((tid & st) == 0);
            bool keepmin = (up == lower);
            K = keepmin ? (K < other ? K : other) : (K > other ? K : other);
        }
    }

    // threads 0..63 hold the top-64 keys -> mark selected columns
    if (tid < KK)
        srow[(int)(K & 0xffffffffu)] = 1.0f;
    __syncthreads();

    g_S[i * BSZ + tid] = srow[tid];
}

// ---------------- tf32 MMA helpers ----------------
__device__ __forceinline__ uint32_t to_tf32(float x) {
    uint32_t r;
    asm("cvt.rna.tf32.f32 %0, %1;" : "=r"(r) : "f"(x));
    return r;
}

__device__ __forceinline__ void mma_tf32(float* c, const uint32_t* a, const uint32_t* b) {
    asm volatile(
        "mma.sync.aligned.m16n8k8.row.col.f32.tf32.tf32.f32 "
        "{%0,%1,%2,%3},{%4,%5,%6,%7},{%8,%9},{%0,%1,%2,%3};"
        : "+f"(c[0]), "+f"(c[1]), "+f"(c[2]), "+f"(c[3])
        : "r"(a[0]), "r"(a[1]), "r"(a[2]), "r"(a[3]), "r"(b[0]), "r"(b[1]));
}

#define GBK  32
#define AST  36
#define BSTN 72

// -------- msg GEMM: msg = (1/64) * S @ local (per-batch blocks) --------
// grid (6 col tiles, 16 row tiles); K=256 (in-batch sources)
__global__ void __launch_bounds__(256) msg_gemm_tc() {
    __shared__ float As[2][64 * AST];
    __shared__ float Bs[2][GBK * BSTN];

    int tid  = threadIdx.x;
    int warp = tid >> 5, lane = tid & 31;
    int wm = (warp & 3) * 16;
    int wn = (warp >> 2) * 32;
    int row0 = blockIdx.y * 64;
    int col0 = blockIdx.x * 64;
    int bsrc = (row0 >> 8) * BSZ;        // batch source row base
    int g  = lane >> 2;
    int tg = lane & 3;

    float acc[4][4] = {};

    int am = tid >> 2;
    int ak = (tid & 3) * 8;
    int bk = tid >> 3;
    int bn = (tid & 7) * 8;

    uint32_t sa0 = (uint32_t)__cvta_generic_to_shared(&As[0][am * AST + ak]);
    uint32_t sa1 = (uint32_t)__cvta_generic_to_shared(&As[1][am * AST + ak]);
    uint32_t sb0 = (uint32_t)__cvta_generic_to_shared(&Bs[0][bk * BSTN + bn]);
    uint32_t sb1 = (uint32_t)__cvta_generic_to_shared(&Bs[1][bk * BSTN + bn]);

#define MSTAGE(it, SA, SB)                                                       \
    {                                                                            \
        int k0 = (it) * GBK;                                                     \
        const float* gp = &g_S[(row0 + am) * BSZ + k0 + ak];                     \
        asm volatile("cp.async.cg.shared.global [%0],[%1],16;" :: "r"(SA), "l"(gp)); \
        asm volatile("cp.async.cg.shared.global [%0],[%1],16;" :: "r"(SA + 16), "l"(gp + 4)); \
        const float* gq = &g_local[(size_t)(bsrc + k0 + bk) * DD + col0 + bn];   \
        asm volatile("cp.async.cg.shared.global [%0],[%1],16;" :: "r"(SB), "l"(gq)); \
        asm volatile("cp.async.cg.shared.global [%0],[%1],16;" :: "r"(SB + 16), "l"(gq + 4)); \
        asm volatile("cp.async.commit_group;");                                  \
    }

    MSTAGE(0, sa0, sb0)

    const int NKM = BSZ / GBK;           // 8 k-iterations
    for (int it = 0; it < NKM; ++it) {
        int cur = it & 1;
        if (it + 1 < NKM) {
            if (cur) MSTAGE(it + 1, sa0, sb0)
            else     MSTAGE(it + 1, sa1, sb1)
            asm volatile("cp.async.wait_group 1;");
        } else {
            asm volatile("cp.async.wait_group 0;");
        }
        __syncthreads();

        const float* A = As[cur];
        const float* B = Bs[cur];
#pragma unroll
        for (int ks = 0; ks < GBK; ks += 8) {
            // S entries are 0/1: exact in tf32, no lo term needed
            uint32_t ah[4] = {
                to_tf32(A[(wm + g) * AST + ks + tg]),
                to_tf32(A[(wm + g + 8) * AST + ks + tg]),
                to_tf32(A[(wm + g) * AST + ks + tg + 4]),
                to_tf32(A[(wm + g + 8) * AST + ks + tg + 4]) };
#pragma unroll
            for (int nj = 0; nj < 4; nj++) {
                float b0 = B[(ks + tg) * BSTN + wn + nj * 8 + g];
                float b1 = B[(ks + tg + 4) * BSTN + wn + nj * 8 + g];
                uint32_t bh[2] = { to_tf32(b0), to_tf32(b1) };
                uint32_t bl[2] = { to_tf32(b0 - __uint_as_float(bh[0])),
                                   to_tf32(b1 - __uint_as_float(bh[1])) };
                mma_tf32(acc[nj], ah, bl);
                mma_tf32(acc[nj], ah, bh);
            }
        }
        __syncthreads();
    }

    int r = row0 + wm + g;
#pragma unroll
    for (int nj = 0; nj < 4; nj++) {
        int c = col0 + wn + nj * 8 + 2 * tg;
        g_msg[r * DD + c]           = acc[nj][0] * 0.015625f;
        g_msg[r * DD + c + 1]       = acc[nj][1] * 0.015625f;
        g_msg[(r + 8) * DD + c]     = acc[nj][2] * 0.015625f;
        g_msg[(r + 8) * DD + c + 1] = acc[nj][3] * 0.015625f;
    }
}

// -------- tf32 GEMM: local += gelu(msg @ Wn), fused pos partials -------
__device__ __forceinline__ float gelu_tanh(float x) {
    float x3 = x * x * x;
    float t = tanhf(0.7978845608028654f * (x + 0.044715f * x3));
    return 0.5f * x * (1.0f + t);
}

#define NKIT (DD / GBK)   // 12

__global__ void __launch_bounds__(256) gemm_gelu_tc(const float* __restrict__ Wn,
                                                    const float* __restrict__ Wp) {
    __shared__ float As[2][64 * AST];
    __shared__ float Bs[2][GBK * BSTN];
    __shared__ float WpS[64 * POSW];

    int tid  = threadIdx.x;
    int warp = tid >> 5, lane = tid & 31;
    int wm = (warp & 3) * 16;
    int wn = (warp >> 2) * 32;
    int row0 = blockIdx.y * 64;
    int col0 = blockIdx.x * 64;
    int g  = lane >> 2;
    int tg = lane & 3;

    float acc[4][4] = {};

    int am = tid >> 2;
    int ak = (tid & 3) * 8;
    int bk = tid >> 3;
    int bn = (tid & 7) * 8;

    uint32_t sa0 = (uint32_t)__cvta_generic_to_shared(&As[0][am * AST + ak]);
    uint32_t sa1 = (uint32_t)__cvta_generic_to_shared(&As[1][am * AST + ak]);
    uint32_t sb0 = (uint32_t)__cvta_generic_to_shared(&Bs[0][bk * BSTN + bn]);
    uint32_t sb1 = (uint32_t)__cvta_generic_to_shared(&Bs[1][bk * BSTN + bn]);

#define STAGE(it, SA, SB)                                                        \
    {                                                                            \
        int k0 = (it) * GBK;                                                     \
        const float* gp = &g_msg[(row0 + am) * DD + k0 + ak];                    \
        asm volatile("cp.async.cg.shared.global [%0],[%1],16;" :: "r"(SA), "l"(gp)); \
        asm volatile("cp.async.cg.shared.global [%0],[%1],16;" :: "r"(SA + 16), "l"(gp + 4)); \
        const float* gq = &Wn[(size_t)(k0 + bk) * DD + col0 + bn];               \
        asm volatile("cp.async.cg.shared.global [%0],[%1],16;" :: "r"(SB), "l"(gq)); \
        asm volatile("cp.async.cg.shared.global [%0],[%1],16;" :: "r"(SB + 16), "l"(gq + 4)); \
        asm volatile("cp.async.commit_group;");                                  \
    }

    STAGE(0, sa0, sb0)

    for (int idx = tid; idx < 64 * POSW; idx += 256)
        WpS[idx] = Wp[col0 * POSW + idx];

    for (int it = 0; it < NKIT; ++it) {
        int cur = it & 1;
        if (it + 1 < NKIT) {
            if (cur) STAGE(it + 1, sa0, sb0)
            else     STAGE(it + 1, sa1, sb1)
            asm volatile("cp.async.wait_group 1;");
        } else {
            asm volatile("cp.async.wait_group 0;");
        }
        __syncthreads();

        const float* A = As[cur];
        const float* B = Bs[cur];
#pragma unroll
        for (int ks = 0; ks < GBK; ks += 8) {
            float a0 = A[(wm + g) * AST + ks + tg];
            float a1 = A[(wm + g + 8) * AST + ks + tg];
            float a2 = A[(wm + g) * AST + ks + tg + 4];
            float a3 = A[(wm + g + 8) * AST + ks + tg + 4];
            uint32_t ah[4] = { to_tf32(a0), to_tf32(a1), to_tf32(a2), to_tf32(a3) };
            uint32_t al[4] = { to_tf32(a0 - __uint_as_float(ah[0])),
                               to_tf32(a1 - __uint_as_float(ah[1])),
                               to_tf32(a2 - __uint_as_float(ah[2])),
                               to_tf32(a3 - __uint_as_float(ah[3])) };
#pragma unroll
            for (int nj = 0; nj < 4; nj++) {
                float b0 = B[(ks + tg) * BSTN + wn + nj * 8 + g];
                float b1 = B[(ks + tg + 4) * BSTN + wn + nj * 8 + g];
                uint32_t bh[2] = { to_tf32(b0), to_tf32(b1) };
                uint32_t bl[2] = { to_tf32(b0 - __uint_as_float(bh[0])),
                                   to_tf32(b1 - __uint_as_float(bh[1])) };
                mma_tf32(acc[nj], al, bh);
                mma_tf32(acc[nj], ah, bl);
                mma_tf32(acc[nj], ah, bh);
            }
        }
        __syncthreads();
    }

    // epilogue: local += gelu(acc); accumulate pos partials over this col block
    int r = row0 + wm + g;
    float pp0[POSW], pp1[POSW];
#pragma unroll
    for (int o = 0; o < POSW; o++) { pp0[o] = 0.0f; pp1[o] = 0.0f; }

#pragma unroll
    for (int nj = 0; nj < 4; nj++) {
        int cl = wn + nj * 8 + 2 * tg;
        int c  = col0 + cl;
        float v00 = g_local[r * DD + c]           + gelu_tanh(acc[nj][0]);
        float v01 = g_local[r * DD + c + 1]       + gelu_tanh(acc[nj][1]);
        float v10 = g_local[(r + 8) * DD + c]     + gelu_tanh(acc[nj][2]);
        float v11 = g_local[(r + 8) * DD + c + 1] + gelu_tanh(acc[nj][3]);
        g_local[r * DD + c]           = v00;
        g_local[r * DD + c + 1]       = v01;
        g_local[(r + 8) * DD + c]     = v10;
        g_local[(r + 8) * DD + c + 1] = v11;
#pragma unroll
        for (int o = 0; o < POSW; o++) {
            float w0 = WpS[cl * POSW + o];
            float w1 = WpS[(cl + 1) * POSW + o];
            pp0[o] += v00 * w0 + v01 * w1;
            pp1[o] += v10 * w0 + v11 * w1;
        }
    }

#pragma unroll
    for (int dlt = 1; dlt <= 2; dlt <<= 1)
#pragma unroll
        for (int o = 0; o < POSW; o++) {
            pp0[o] += __shfl_xor_sync(0xFFFFFFFFu, pp0[o], dlt);
            pp1[o] += __shfl_xor_sync(0xFFFFFFFFu, pp1[o], dlt);
        }

    if (tg == 0) {
        int slot = blockIdx.x * 2 + (wn >> 5);
        float* pb = &g_pospart[(size_t)slot * (NN * POSW)];
#pragma unroll
        for (int o = 0; o < POSW; o++) {
            pb[r * POSW + o]       = pp0[o];
            pb[(r + 8) * POSW + o] = pp1[o];
        }
    }
}

// ---------------- kernel: finalize pos + trajectory write --------------
__global__ void __launch_bounds__(256) finalize_pos(float* __restrict__ traj_out) {
    int gidx = blockIdx.x * 256 + threadIdx.x;             // 60 blocks x 256 = 15360
    float acc = 0.0f;
#pragma unroll
    for (int cb = 0; cb < NPART; cb++)
        acc += g_pospart[(size_t)cb * (NN * POSW) + gidx];
    float p = g_pos[gidx] + 0.1f * acc;
    g_pos[gidx] = p;
    traj_out[gidx] = p;
}

// ---------------- launch ----------------
extern "C" void kernel_launch(void* const* d_in, const int* in_sizes, int n_in,
                              void* d_out, int out_size) {
    const float* local    = (const float*)d_in[0];
    const float* pos      = (const float*)d_in[1];
    const float* prev_pos = (const float*)d_in[2];
    const float* disto    = (const float*)d_in[3];
    const float* Wn       = (const float*)d_in[4];
    const float* Wp       = (const float*)d_in[5];
    const int*   resi     = (const int*)d_in[6];
    const int*   chain    = (const int*)d_in[7];
    const int*   batch    = (const int*)d_in[8];
    float* out = (float*)d_out;

    cudaMemcpyToSymbolAsync(g_local, local, (size_t)NN * DD * sizeof(float), 0,
                            cudaMemcpyDeviceToDevice, 0);
    cudaMemcpyToSymbolAsync(g_pos, pos, (size_t)NN * POSW * sizeof(float), 0,
                            cudaMemcpyDeviceToDevice, 0);

    based_kernel<<<NN * BSZ / 256, 256>>>(prev_pos, disto, resi, chain, batch);

    uint32_t fk0[NDEPTH], fk1[NDEPTH];
    for (int t = 0; t < NDEPTH; t++)
        tf2x32(0u, 42u, 0u, (uint32_t)t, fk0[t], fk1[t]);

    float* traj_base = out + (size_t)NN * DD + (size_t)NN * POSW;
    dim3 ggrid(DD / 64, NN / 64);

    for (int t = 0; t < NDEPTH; t++) {
        topk_kernel<<<NN, BSZ>>>(fk0[t], fk1[t], batch);
        msg_gemm_tc<<<ggrid, 256>>>();
        gemm_gelu_tc<<<ggrid, 256>>>(Wn, Wp);
        finalize_pos<<<NN * POSW / 256, 256>>>(traj_base + (size_t)t * NN * POSW);
    }

    cudaMemcpyFromSymbolAsync(out, g_local, (size_t)NN * DD * sizeof(float), 0,
                              cudaMemcpyDeviceToDevice, 0);
    cudaMemcpyFromSymbolAsync(out + (size_t)NN * DD, g_pos,
                              (size_t)NN * POSW * sizeof(float), 0,
                              cudaMemcpyDeviceToDevice, 0);
}